// round 1
// baseline (speedup 1.0000x reference)
#include <cuda_runtime.h>
#include <cstdint>

#define NEXP 64
#define KDIM 1024
#define NROWS 131072
#define HIGH_NEG -100000.0f

// Exact column-quantile ranks (ascending, 0-based): pos = 0.75*131071 = 98303.25
#define CRANK0 98303u
#define CRANK1 98304u

// ---------------- scratch (device globals; no allocation allowed) ----------------
__device__ uint32_t g_hist1[NEXP * 65536];
__device__ uint32_t g_hist2[NEXP * 65536];
__device__ uint32_t g_minb1[NEXP];
__device__ uint32_t g_bkt0[NEXP], g_rnk0[NEXP], g_bkt1[NEXP], g_rnk1[NEXP];
__device__ float    g_tcol[NEXP];

// monotone float -> uint mapping (total order == float order)
__device__ __forceinline__ uint32_t f2o(float f) {
    uint32_t u = __float_as_uint(f);
    return u ^ ((u & 0x80000000u) ? 0xFFFFFFFFu : 0x80000000u);
}
__device__ __forceinline__ float o2f(uint32_t u) {
    u ^= ((u & 0x80000000u) ? 0x80000000u : 0xFFFFFFFFu);
    return __uint_as_float(u);
}

// ---------------- zero scratch (must run every replay; graph-safe) ----------------
__global__ void zero_hists() {
    const int n = NEXP * 65536;
    for (int i = blockIdx.x * blockDim.x + threadIdx.x; i < n;
         i += gridDim.x * blockDim.x) {
        g_hist1[i] = 0u;
        g_hist2[i] = 0u;
    }
    if (blockIdx.x == 0 && threadIdx.x < NEXP) g_minb1[threadIdx.x] = 0xFFFFFFFFu;
}

// ---------------- GEMM: logits = x @ W^T + b + 0.1*noise -> out ----------------
// BM=128 rows, all 64 experts, BK=32. 256 threads (16x16), thread tile 8x4.
#define BM 128
#define BK 32
__global__ __launch_bounds__(256) void gemm_kernel(
    const float* __restrict__ x, const float* __restrict__ W,
    const float* __restrict__ bias, const float* __restrict__ noise,
    float* __restrict__ out)
{
    __shared__ float As[BM][BK + 1];     // 128 x 33
    __shared__ float Ws[BK][NEXP + 4];   // 32 x 68 (row stride 272B, 16B aligned)

    const int tid = threadIdx.x;
    const int tx = tid & 15;          // expert group: experts tx*4 .. tx*4+3
    const int ty = tid >> 4;          // row group:    rows ty*8 .. ty*8+7
    const int rowBase = blockIdx.x * BM;

    float acc[8][4];
#pragma unroll
    for (int i = 0; i < 8; i++)
#pragma unroll
        for (int j = 0; j < 4; j++) acc[i][j] = 0.0f;

    for (int k0 = 0; k0 < KDIM; k0 += BK) {
        // load A tile: 4096 floats, 16/thread, coalesced
#pragma unroll
        for (int i = 0; i < 16; i++) {
            int lin = tid + i * 256;
            int r = lin >> 5, c = lin & 31;
            As[r][c] = x[(rowBase + r) * KDIM + k0 + c];
        }
        // load W tile transposed: 2048 floats, 8/thread, coalesced read
#pragma unroll
        for (int i = 0; i < 8; i++) {
            int lin = tid + i * 256;
            int e = lin >> 5, c = lin & 31;
            Ws[c][e] = W[e * KDIM + k0 + c];
        }
        __syncthreads();

#pragma unroll
        for (int kk = 0; kk < BK; kk++) {
            float4 wv = *reinterpret_cast<const float4*>(&Ws[kk][tx * 4]);
            float av[8];
#pragma unroll
            for (int i = 0; i < 8; i++) av[i] = As[ty * 8 + i][kk];
#pragma unroll
            for (int i = 0; i < 8; i++) {
                acc[i][0] = fmaf(av[i], wv.x, acc[i][0]);
                acc[i][1] = fmaf(av[i], wv.y, acc[i][1]);
                acc[i][2] = fmaf(av[i], wv.z, acc[i][2]);
                acc[i][3] = fmaf(av[i], wv.w, acc[i][3]);
            }
        }
        __syncthreads();
    }

    const int e0 = tx * 4;
    float4 bv = *reinterpret_cast<const float4*>(&bias[e0]);
#pragma unroll
    for (int i = 0; i < 8; i++) {
        int row = rowBase + ty * 8 + i;
        float4 nz = *reinterpret_cast<const float4*>(&noise[row * NEXP + e0]);
        float4 o;
        o.x = (acc[i][0] + bv.x) + 0.1f * nz.x;
        o.y = (acc[i][1] + bv.y) + 0.1f * nz.y;
        o.z = (acc[i][2] + bv.z) + 0.1f * nz.z;
        o.w = (acc[i][3] + bv.w) + 0.1f * nz.w;
        *reinterpret_cast<float4*>(&out[row * NEXP + e0]) = o;
    }
}

// ---------------- column quantile, level-1 histogram (top 16 bits) ----------------
__global__ void hist_pass1(const float4* __restrict__ lg, int n4) {
    for (int i = blockIdx.x * blockDim.x + threadIdx.x; i < n4;
         i += gridDim.x * blockDim.x) {
        float4 v = lg[i];
        int col = (i * 4) & 63;
        atomicAdd(&g_hist1[((col + 0) << 16) | (f2o(v.x) >> 16)], 1u);
        atomicAdd(&g_hist1[((col + 1) << 16) | (f2o(v.y) >> 16)], 1u);
        atomicAdd(&g_hist1[((col + 2) << 16) | (f2o(v.z) >> 16)], 1u);
        atomicAdd(&g_hist1[((col + 3) << 16) | (f2o(v.w) >> 16)], 1u);
    }
}

// scan level-1 hist per column: locate buckets containing ranks CRANK0/CRANK1
__global__ void find_bucket1() {
    const int e = blockIdx.x;
    const uint32_t* h = &g_hist1[e << 16];
    const int t = threadIdx.x;  // 256 threads, 256 bins each
    __shared__ uint32_t partial[256];
    __shared__ uint32_t pref[257];
    uint32_t s = 0;
    for (int i = 0; i < 256; i++) s += h[t * 256 + i];
    partial[t] = s;
    __syncthreads();
    if (t == 0) {
        uint32_t c = 0;
        pref[0] = 0;
        for (int i = 0; i < 256; i++) { c += partial[i]; pref[i + 1] = c; }
    }
    __syncthreads();
    const uint32_t ranks[2] = {CRANK0, CRANK1};
    for (int ri = 0; ri < 2; ri++) {
        uint32_t r = ranks[ri];
        if (pref[t] <= r && r < pref[t + 1]) {
            uint32_t cum = pref[t];
            for (int i = 0; i < 256; i++) {
                uint32_t c = h[t * 256 + i];
                if (r < cum + c) {
                    if (ri == 0) { g_bkt0[e] = (uint32_t)(t * 256 + i); g_rnk0[e] = r - cum; }
                    else         { g_bkt1[e] = (uint32_t)(t * 256 + i); g_rnk1[e] = r - cum; }
                    break;
                }
                cum += c;
            }
        }
    }
}

// level-2 histogram (low 16 bits) restricted to the rank-0 bucket; min of rank-1 bucket
__global__ void hist_pass2(const float4* __restrict__ lg, int n4) {
    __shared__ uint32_t b0s[NEXP], b1s[NEXP];
    if (threadIdx.x < NEXP) {
        b0s[threadIdx.x] = g_bkt0[threadIdx.x];
        b1s[threadIdx.x] = g_bkt1[threadIdx.x];
    }
    __syncthreads();
    for (int i = blockIdx.x * blockDim.x + threadIdx.x; i < n4;
         i += gridDim.x * blockDim.x) {
        float4 v = lg[i];
        int col = (i * 4) & 63;
        float vals[4] = {v.x, v.y, v.z, v.w};
#pragma unroll
        for (int j = 0; j < 4; j++) {
            uint32_t u = f2o(vals[j]);
            uint32_t hb = u >> 16;
            int c = col + j;
            if (hb == b0s[c]) atomicAdd(&g_hist2[(c << 16) | (u & 0xFFFFu)], 1u);
            if (hb == b1s[c]) atomicMin(&g_minb1[c], u);
        }
    }
}

// scan level-2 hist: recover exact order statistics, build column thresholds
__global__ void find_bucket2() {
    const int e = blockIdx.x;
    const uint32_t b0 = g_bkt0[e], b1 = g_bkt1[e];
    const uint32_t r0 = g_rnk0[e], r1 = g_rnk1[e];
    const uint32_t* h = &g_hist2[e << 16];
    const int t = threadIdx.x;
    __shared__ uint32_t partial[256];
    __shared__ uint32_t pref[257];
    __shared__ uint32_t lowbits[2];
    uint32_t s = 0;
    for (int i = 0; i < 256; i++) s += h[t * 256 + i];
    partial[t] = s;
    __syncthreads();
    if (t == 0) {
        uint32_t c = 0;
        pref[0] = 0;
        for (int i = 0; i < 256; i++) { c += partial[i]; pref[i + 1] = c; }
    }
    __syncthreads();
    const int nt = (b0 == b1) ? 2 : 1;
    const uint32_t ranks[2] = {r0, r1};
    for (int ri = 0; ri < nt; ri++) {
        uint32_t r = ranks[ri];
        if (pref[t] <= r && r < pref[t + 1]) {
            uint32_t cum = pref[t];
            for (int i = 0; i < 256; i++) {
                uint32_t c = h[t * 256 + i];
                if (r < cum + c) { lowbits[ri] = (uint32_t)(t * 256 + i); break; }
                cum += c;
            }
        }
    }
    __syncthreads();
    if (t == 0) {
        uint32_t s0bits = (b0 << 16) | lowbits[0];
        uint32_t s1bits = (b0 == b1) ? ((b0 << 16) | lowbits[1]) : g_minb1[e];
        float s0 = o2f(s0bits);
        float s1 = o2f(s1bits);
        // quantile linear interp at frac 0.25 (exact order stats -> mask is exact)
        g_tcol[e] = s0 + 0.25f * (s1 - s0);
    }
}

// ---------------- row pass: capacity mask + per-row top-2 quantile mask + softmax --
__global__ __launch_bounds__(256) void row_kernel(float* __restrict__ lg) {
    __shared__ float tc[NEXP];
    const int tid = threadIdx.x;
    if (tid < NEXP) tc[tid] = g_tcol[tid];
    __syncthreads();
    const int lane = tid & 31;
    const int w = tid >> 5;
    const int row = blockIdx.x * 8 + w;

    float v0 = lg[row * NEXP + lane];
    float v1 = lg[row * NEXP + 32 + lane];
    // capacity mask: keep iff strictly above column threshold
    float m0 = (v0 > tc[lane])      ? v0 : HIGH_NEG;
    float m1 = (v1 > tc[lane + 32]) ? v1 : HIGH_NEG;

    // warp top-3 (descending a>=b>=c) via sorted-triple merge
    float a = fmaxf(m0, m1), b = fminf(m0, m1), c = -3.402823466e38f;
#pragma unroll
    for (int off = 16; off > 0; off >>= 1) {
        float a2 = __shfl_xor_sync(0xffffffffu, a, off);
        float b2 = __shfl_xor_sync(0xffffffffu, b, off);
        float c2 = __shfl_xor_sync(0xffffffffu, c, off);
        float o1, o2, o3;
        if (a >= a2) {
            o1 = a;
            if (b >= a2) { o2 = b;  o3 = fmaxf(c, a2); }
            else         { o2 = a2; o3 = fmaxf(b, b2); }
        } else {
            o1 = a2;
            if (b2 >= a) { o2 = b2; o3 = fmaxf(c2, a); }
            else         { o2 = a;  o3 = fmaxf(b, b2); }
        }
        a = o1; b = o2; c = o3;
    }
    // row quantile at pos 61.03125: thr = s[61] + 0.03125*(s[62]-s[61])
    float thr = c + 0.03125f * (b - c);
    float w0 = (m0 > thr) ? m0 : HIGH_NEG;
    float w1 = (m1 > thr) ? m1 : HIGH_NEG;
    float M = (a > thr) ? a : HIGH_NEG;   // row max after masking

    float e0 = expf(w0 - M);              // masked entries underflow to exact 0
    float e1 = expf(w1 - M);
    float ssum = e0 + e1;
#pragma unroll
    for (int off = 16; off > 0; off >>= 1)
        ssum += __shfl_xor_sync(0xffffffffu, ssum, off);

    lg[row * NEXP + lane]      = e0 / ssum;
    lg[row * NEXP + 32 + lane] = e1 / ssum;
}

// ---------------- launch ----------------
extern "C" void kernel_launch(void* const* d_in, const int* in_sizes, int n_in,
                              void* d_out, int out_size) {
    const float *x = nullptr, *noise = nullptr, *W = nullptr, *bias = nullptr;
    for (int i = 0; i < n_in; i++) {
        switch (in_sizes[i]) {
            case NROWS * KDIM: x     = (const float*)d_in[i]; break; // 134217728
            case NROWS * NEXP: noise = (const float*)d_in[i]; break; //   8388608
            case NEXP * KDIM:  W     = (const float*)d_in[i]; break; //     65536
            case NEXP:         bias  = (const float*)d_in[i]; break; //        64
            default: break;
        }
    }
    float* out = (float*)d_out;
    const int n4 = NROWS * NEXP / 4;

    zero_hists<<<2048, 256>>>();
    gemm_kernel<<<NROWS / BM, 256>>>(x, W, bias, noise, out);
    hist_pass1<<<4096, 256>>>((const float4*)out, n4);
    find_bucket1<<<NEXP, 256>>>();
    hist_pass2<<<4096, 256>>>((const float4*)out, n4);
    find_bucket2<<<NEXP, 256>>>();
    row_kernel<<<NROWS / 8, 256>>>(out);
}

// round 3
// speedup vs baseline: 2.3642x; 2.3642x over previous
#include <cuda_runtime.h>
#include <cuda_bf16.h>
#include <cstdint>

#define NEXP 64
#define KDIM 1024
#define NROWS 131072
#define HIGH_NEG -100000.0f
#define CRANK0 98303u
#define CRANK1 98304u

// ---------------- scratch ----------------
__device__ uint32_t g_hist1[NEXP * 65536];
__device__ uint32_t g_hist2[NEXP * 65536];
__device__ uint32_t g_minb1[NEXP];
__device__ uint32_t g_bkt0[NEXP], g_rnk0[NEXP], g_bkt1[NEXP], g_rnk1[NEXP];
__device__ float    g_tcol[NEXP];
__device__ __nv_bfloat16 g_whi[NEXP * KDIM];
__device__ __nv_bfloat16 g_wlo[NEXP * KDIM];

// ---------------- helpers ----------------
__device__ __forceinline__ uint32_t f2o(float f) {
    uint32_t u = __float_as_uint(f);
    return u ^ ((u & 0x80000000u) ? 0xFFFFFFFFu : 0x80000000u);
}
__device__ __forceinline__ float o2f(uint32_t u) {
    u ^= ((u & 0x80000000u) ? 0x80000000u : 0xFFFFFFFFu);
    return __uint_as_float(u);
}
__device__ __forceinline__ uint32_t smem_u32(const void* p) {
    uint32_t a;
    asm("{ .reg .u64 t; cvta.to.shared.u64 t, %1; cvt.u32.u64 %0, t; }" : "=r"(a) : "l"(p));
    return a;
}
__device__ __forceinline__ void ldmx4(uint32_t* r, uint32_t addr) {
    asm volatile("ldmatrix.sync.aligned.m8n8.x4.shared.b16 {%0,%1,%2,%3}, [%4];"
                 : "=r"(r[0]), "=r"(r[1]), "=r"(r[2]), "=r"(r[3]) : "r"(addr));
}
__device__ __forceinline__ void mma_bf16(float* d, const uint32_t* a,
                                         uint32_t b0, uint32_t b1) {
    asm volatile(
        "mma.sync.aligned.m16n8k16.row.col.f32.bf16.bf16.f32 "
        "{%0,%1,%2,%3}, {%4,%5,%6,%7}, {%8,%9}, {%0,%1,%2,%3};"
        : "+f"(d[0]), "+f"(d[1]), "+f"(d[2]), "+f"(d[3])
        : "r"(a[0]), "r"(a[1]), "r"(a[2]), "r"(a[3]), "r"(b0), "r"(b1));
}

// ---------------- zero scratch ----------------
__global__ void zero_hists() {
    uint4* a = reinterpret_cast<uint4*>(g_hist1);
    uint4* b = reinterpret_cast<uint4*>(g_hist2);
    const int n = NEXP * 65536 / 4;
    uint4 z = make_uint4(0u, 0u, 0u, 0u);
    for (int i = blockIdx.x * blockDim.x + threadIdx.x; i < n;
         i += gridDim.x * blockDim.x) {
        a[i] = z;
        b[i] = z;
    }
    if (blockIdx.x == 0 && threadIdx.x < NEXP) g_minb1[threadIdx.x] = 0xFFFFFFFFu;
}

// ---------------- W -> bf16 hi/lo ----------------
__global__ void w_convert(const float* __restrict__ W) {
    int i = blockIdx.x * blockDim.x + threadIdx.x;
    float v = W[i];
    __nv_bfloat16 h = __float2bfloat16(v);
    g_whi[i] = h;
    g_wlo[i] = __float2bfloat16(v - __bfloat162float(h));
}

// ---------------- mma.sync GEMM: out = x @ W^T + b + 0.1*noise (+ fused hist1) ----
#define BM 128
#define CHUNK 64
#define NCH (KDIM / CHUNK)
// padded bf16 row stride: 72 elems = 144 bytes (conflict-free ldmatrix)
#define RS 72
#define SM_A_HI 0
#define SM_A_LO 18432
#define SM_B_HI 36864
#define SM_B_LO 46080
#define SMEM_TOTAL 55296
#define STG 68   // staging row stride in floats (272B, 16B-aligned rows)

__global__ __launch_bounds__(256, 2) void gemm_mma(
    const float* __restrict__ x, const float* __restrict__ bias,
    const float* __restrict__ noise, float* __restrict__ out)
{
    extern __shared__ char smem[];
    const uint32_t sb = smem_u32(smem);
    const int tid = threadIdx.x;
    const int wid = tid >> 5, lid = tid & 31;
    const int wm = wid >> 2, wn = wid & 3;     // warp grid 2 x 4
    const int rowBase = blockIdx.x * BM;
    const float* xr = x + (size_t)rowBase * KDIM;

    float acc[4][2][4];
#pragma unroll
    for (int mi = 0; mi < 4; mi++)
#pragma unroll
        for (int ni = 0; ni < 2; ni++)
#pragma unroll
            for (int j = 0; j < 4; j++) acc[mi][ni][j] = 0.0f;

    // ldmatrix source addresses (fixed per thread, per-kstep offset added later)
    const int a_row = wm * 64 + (lid & 15);
    const uint32_t asel = (uint32_t)((lid >> 4) * 16);          // k-half byte offset
    const uint32_t aoffH = sb + SM_A_HI + (uint32_t)a_row * 144 + asel;
    const uint32_t aoffL = sb + SM_A_LO + (uint32_t)a_row * 144 + asel;
    const int b_row = wn * 16 + ((lid >> 4) << 3) + (lid & 7);
    const uint32_t bsel = (uint32_t)(((lid >> 3) & 1) * 16);
    const uint32_t boffH = sb + SM_B_HI + (uint32_t)b_row * 144 + bsel;
    const uint32_t boffL = sb + SM_B_LO + (uint32_t)b_row * 144 + bsel;

    float4 xbuf[8];
#pragma unroll
    for (int i = 0; i < 8; i++) {
        int l = tid + i * 256;
        xbuf[i] = *reinterpret_cast<const float4*>(xr + (size_t)(l >> 4) * KDIM + (l & 15) * 4);
    }

    for (int c = 0; c < NCH; c++) {
        const int kc = c * CHUNK;
        // ---- convert x chunk to hi/lo bf16, store padded ----
#pragma unroll
        for (int i = 0; i < 8; i++) {
            int l = tid + i * 256;
            int r = l >> 4, q = l & 15;
            float4 v = xbuf[i];
            uint32_t h01, h23, l01, l23;
            asm("cvt.rn.bf16x2.f32 %0, %1, %2;" : "=r"(h01) : "f"(v.y), "f"(v.x));
            asm("cvt.rn.bf16x2.f32 %0, %1, %2;" : "=r"(h23) : "f"(v.w), "f"(v.z));
            float r0 = v.x - __uint_as_float(h01 << 16);
            float r1 = v.y - __uint_as_float(h01 & 0xFFFF0000u);
            float r2 = v.z - __uint_as_float(h23 << 16);
            float r3 = v.w - __uint_as_float(h23 & 0xFFFF0000u);
            asm("cvt.rn.bf16x2.f32 %0, %1, %2;" : "=r"(l01) : "f"(r1), "f"(r0));
            asm("cvt.rn.bf16x2.f32 %0, %1, %2;" : "=r"(l23) : "f"(r3), "f"(r2));
            uint32_t off = (uint32_t)(r * 144 + q * 8);
            *reinterpret_cast<uint2*>(smem + SM_A_HI + off) = make_uint2(h01, h23);
            *reinterpret_cast<uint2*>(smem + SM_A_LO + off) = make_uint2(l01, l23);
        }
        // ---- stage W hi/lo tiles (pre-split) ----
        {
            const uint4* wh = reinterpret_cast<const uint4*>(g_whi);
            const uint4* wl = reinterpret_cast<const uint4*>(g_wlo);
#pragma unroll
            for (int i = 0; i < 2; i++) {
                int l = tid + i * 256;
                int e = l >> 3, q = l & 7;
                uint32_t src = (uint32_t)(e * KDIM + kc) >> 3;
                uint32_t off = (uint32_t)(e * 144 + q * 16);
                *reinterpret_cast<uint4*>(smem + SM_B_HI + off) = wh[src + q];
                *reinterpret_cast<uint4*>(smem + SM_B_LO + off) = wl[src + q];
            }
        }
        __syncthreads();

        // ---- prefetch next chunk ----
        if (c + 1 < NCH) {
            const int kn = kc + CHUNK;
#pragma unroll
            for (int i = 0; i < 8; i++) {
                int l = tid + i * 256;
                xbuf[i] = *reinterpret_cast<const float4*>(
                    xr + (size_t)(l >> 4) * KDIM + kn + (l & 15) * 4);
            }
        }

        // ---- mma over chunk: 4 ksteps x (hi*hi + hi*lo + lo*hi) ----
#pragma unroll
        for (int kk = 0; kk < 4; kk++) {
            uint32_t bh[4], bl[4];
            ldmx4(bh, boffH + kk * 32);
            ldmx4(bl, boffL + kk * 32);
            uint32_t ah[4][4], al[4][4];
#pragma unroll
            for (int mi = 0; mi < 4; mi++) {
                ldmx4(ah[mi], aoffH + (uint32_t)(mi * 16 * 144) + kk * 32);
                ldmx4(al[mi], aoffL + (uint32_t)(mi * 16 * 144) + kk * 32);
            }
#pragma unroll
            for (int mi = 0; mi < 4; mi++) {
#pragma unroll
                for (int ni = 0; ni < 2; ni++) {
                    mma_bf16(acc[mi][ni], ah[mi], bh[ni * 2], bh[ni * 2 + 1]);
                    mma_bf16(acc[mi][ni], ah[mi], bl[ni * 2], bl[ni * 2 + 1]);
                    mma_bf16(acc[mi][ni], al[mi], bh[ni * 2], bh[ni * 2 + 1]);
                }
            }
        }
        __syncthreads();
    }

    // ---- epilogue: stage accs in smem (reuse), coalesced write + fused hist1 ----
    float* stg = reinterpret_cast<float*>(smem);
#pragma unroll
    for (int mi = 0; mi < 4; mi++) {
        int row = wm * 64 + mi * 16 + (lid >> 2);
        int col = wn * 16 + 2 * (lid & 3);
#pragma unroll
        for (int ni = 0; ni < 2; ni++) {
            int cc = col + ni * 8;
            *reinterpret_cast<float2*>(&stg[row * STG + cc]) =
                make_float2(acc[mi][ni][0], acc[mi][ni][1]);
            *reinterpret_cast<float2*>(&stg[(row + 8) * STG + cc]) =
                make_float2(acc[mi][ni][2], acc[mi][ni][3]);
        }
    }
    __syncthreads();

    const float* nz = noise + (size_t)rowBase * NEXP;
    float* op = out + (size_t)rowBase * NEXP;
#pragma unroll
    for (int j = 0; j < 8; j++) {
        int l = tid + j * 256;
        int r = l >> 4, q = (l & 15) * 4;
        float4 nv = *reinterpret_cast<const float4*>(nz + r * NEXP + q);
        float4 bv = *reinterpret_cast<const float4*>(bias + q);
        float4 o;
        o.x = (stg[r * STG + q + 0] + bv.x) + 0.1f * nv.x;
        o.y = (stg[r * STG + q + 1] + bv.y) + 0.1f * nv.y;
        o.z = (stg[r * STG + q + 2] + bv.z) + 0.1f * nv.z;
        o.w = (stg[r * STG + q + 3] + bv.w) + 0.1f * nv.w;
        *reinterpret_cast<float4*>(op + r * NEXP + q) = o;
        atomicAdd(&g_hist1[((q + 0) << 16) | (f2o(o.x) >> 16)], 1u);
        atomicAdd(&g_hist1[((q + 1) << 16) | (f2o(o.y) >> 16)], 1u);
        atomicAdd(&g_hist1[((q + 2) << 16) | (f2o(o.z) >> 16)], 1u);
        atomicAdd(&g_hist1[((q + 3) << 16) | (f2o(o.w) >> 16)], 1u);
    }
}

// ---------------- fast bucket-finders ----------------
__device__ __forceinline__ uint32_t warp_iscan(uint32_t v, int lane) {
#pragma unroll
    for (int o = 1; o < 32; o <<= 1) {
        uint32_t t = __shfl_up_sync(0xffffffffu, v, o);
        if (lane >= o) v += t;
    }
    return v;
}

__device__ void scan_hist(const uint32_t* __restrict__ h, const uint32_t* ranks, int nt,
                          uint32_t* out_bin, uint32_t* out_rnk) {
    __shared__ uint32_t gsum[256];
    __shared__ uint32_t gpref[257];
    __shared__ uint32_t s_grp[2], s_base[2];
    const int tid = threadIdx.x, lane = tid & 31, w = tid >> 5;

    for (int g = w * 32; g < w * 32 + 32; g++) {
        uint32_t s = 0;
#pragma unroll
        for (int j = 0; j < 8; j++) s += h[g * 256 + j * 32 + lane];
#pragma unroll
        for (int o = 16; o; o >>= 1) s += __shfl_xor_sync(0xffffffffu, s, o);
        if (lane == 0) gsum[g] = s;
    }
    __syncthreads();
    if (w == 0) {
        uint32_t run = 0;
#pragma unroll
        for (int j = 0; j < 8; j++) {
            uint32_t v = gsum[j * 32 + lane];
            uint32_t pv = warp_iscan(v, lane);
            gpref[j * 32 + lane + 1] = run + pv;
            run += __shfl_sync(0xffffffffu, pv, 31);
        }
        if (lane == 0) gpref[0] = 0;
    }
    __syncthreads();
    for (int ri = 0; ri < nt; ri++) {
        uint32_t r = ranks[ri];
        if (gpref[tid] <= r && r < gpref[tid + 1]) { s_grp[ri] = tid; s_base[ri] = gpref[tid]; }
    }
    __syncthreads();
    if (w == 0) {
        for (int ri = 0; ri < nt; ri++) {
            uint32_t g = s_grp[ri], r = ranks[ri];
            uint32_t cum = s_base[ri];
#pragma unroll
            for (int j = 0; j < 8; j++) {
                uint32_t v = h[g * 256 + j * 32 + lane];
                uint32_t pv = warp_iscan(v, lane);
                uint32_t tot = __shfl_sync(0xffffffffu, pv, 31);
                uint32_t lo = cum + pv - v;
                if (v && lo <= r && r < cum + pv) {
                    out_bin[ri] = g * 256 + j * 32 + lane;
                    out_rnk[ri] = r - lo;
                }
                cum += tot;
            }
        }
    }
    __syncthreads();
}

__global__ void find_bucket1_v2() {
    const int e = blockIdx.x;
    __shared__ uint32_t bin[2], rnk[2];
    const uint32_t ranks[2] = {CRANK0, CRANK1};
    scan_hist(&g_hist1[e << 16], ranks, 2, bin, rnk);
    if (threadIdx.x == 0) {
        g_bkt0[e] = bin[0]; g_rnk0[e] = rnk[0];
        g_bkt1[e] = bin[1]; g_rnk1[e] = rnk[1];
    }
}

__global__ void find_bucket2_v2() {
    const int e = blockIdx.x;
    const uint32_t b0 = g_bkt0[e], b1 = g_bkt1[e];
    const int nt = (b0 == b1) ? 2 : 1;
    __shared__ uint32_t bin[2], rnk[2];
    const uint32_t ranks[2] = {g_rnk0[e], g_rnk1[e]};
    scan_hist(&g_hist2[e << 16], ranks, nt, bin, rnk);
    if (threadIdx.x == 0) {
        uint32_t s0bits = (b0 << 16) | bin[0];
        uint32_t s1bits = (nt == 2) ? ((b0 << 16) | bin[1]) : g_minb1[e];
        float s0 = o2f(s0bits), s1 = o2f(s1bits);
        g_tcol[e] = s0 + 0.25f * (s1 - s0);
    }
}

// ---------------- hist pass 2 ----------------
__global__ void hist_pass2(const float4* __restrict__ lg, int n4) {
    __shared__ uint32_t b0s[NEXP], b1s[NEXP];
    if (threadIdx.x < NEXP) {
        b0s[threadIdx.x] = g_bkt0[threadIdx.x];
        b1s[threadIdx.x] = g_bkt1[threadIdx.x];
    }
    __syncthreads();
    for (int i = blockIdx.x * blockDim.x + threadIdx.x; i < n4;
         i += gridDim.x * blockDim.x) {
        float4 v = lg[i];
        int col = (i * 4) & 63;
        float vals[4] = {v.x, v.y, v.z, v.w};
#pragma unroll
        for (int j = 0; j < 4; j++) {
            uint32_t u = f2o(vals[j]);
            uint32_t hb = u >> 16;
            int c = col + j;
            if (hb == b0s[c]) atomicAdd(&g_hist2[(c << 16) | (u & 0xFFFFu)], 1u);
            if (hb == b1s[c]) atomicMin(&g_minb1[c], u);
        }
    }
}

// ---------------- row pass ----------------
__global__ __launch_bounds__(256) void row_kernel(float* __restrict__ lg) {
    __shared__ float tc[NEXP];
    const int tid = threadIdx.x;
    if (tid < NEXP) tc[tid] = g_tcol[tid];
    __syncthreads();
    const int lane = tid & 31;
    const int w = tid >> 5;
    const int row = blockIdx.x * 8 + w;

    float v0 = lg[row * NEXP + lane];
    float v1 = lg[row * NEXP + 32 + lane];
    float m0 = (v0 > tc[lane])      ? v0 : HIGH_NEG;
    float m1 = (v1 > tc[lane + 32]) ? v1 : HIGH_NEG;

    float a = fmaxf(m0, m1), b = fminf(m0, m1), c = -3.402823466e38f;
#pragma unroll
    for (int off = 16; off > 0; off >>= 1) {
        float a2 = __shfl_xor_sync(0xffffffffu, a, off);
        float b2 = __shfl_xor_sync(0xffffffffu, b, off);
        float c2 = __shfl_xor_sync(0xffffffffu, c, off);
        float o1, o2, o3;
        if (a >= a2) {
            o1 = a;
            if (b >= a2) { o2 = b;  o3 = fmaxf(c, a2); }
            else         { o2 = a2; o3 = fmaxf(b, b2); }
        } else {
            o1 = a2;
            if (b2 >= a) { o2 = b2; o3 = fmaxf(c2, a); }
            else         { o2 = a;  o3 = fmaxf(b, b2); }
        }
        a = o1; b = o2; c = o3;
    }
    float thr = c + 0.03125f * (b - c);
    float w0 = (m0 > thr) ? m0 : HIGH_NEG;
    float w1 = (m1 > thr) ? m1 : HIGH_NEG;
    float M = (a > thr) ? a : HIGH_NEG;

    float e0 = expf(w0 - M);
    float e1 = expf(w1 - M);
    float ssum = e0 + e1;
#pragma unroll
    for (int off = 16; off > 0; off >>= 1)
        ssum += __shfl_xor_sync(0xffffffffu, ssum, off);

    lg[row * NEXP + lane]      = e0 / ssum;
    lg[row * NEXP + 32 + lane] = e1 / ssum;
}

// ---------------- launch ----------------
extern "C" void kernel_launch(void* const* d_in, const int* in_sizes, int n_in,
                              void* d_out, int out_size) {
    const float *x = nullptr, *noise = nullptr, *W = nullptr, *bias = nullptr;
    for (int i = 0; i < n_in; i++) {
        switch (in_sizes[i]) {
            case NROWS * KDIM: x     = (const float*)d_in[i]; break;
            case NROWS * NEXP: noise = (const float*)d_in[i]; break;
            case NEXP * KDIM:  W     = (const float*)d_in[i]; break;
            case NEXP:         bias  = (const float*)d_in[i]; break;
            default: break;
        }
    }
    float* out = (float*)d_out;
    const int n4 = NROWS * NEXP / 4;

    cudaFuncSetAttribute(gemm_mma, cudaFuncAttributeMaxDynamicSharedMemorySize, SMEM_TOTAL);

    zero_hists<<<2048, 256>>>();
    w_convert<<<NEXP * KDIM / 256, 256>>>(W);
    gemm_mma<<<NROWS / BM, 256, SMEM_TOTAL>>>(x, bias, noise, out);
    find_bucket1_v2<<<NEXP, 256>>>();
    hist_pass2<<<4096, 256>>>((const float4*)out, n4);
    find_bucket2_v2<<<NEXP, 256>>>();
    row_kernel<<<NROWS / 8, 256>>>(out);
}